// round 11
// baseline (speedup 1.0000x reference)
#include <cuda_runtime.h>
#include <math_constants.h>

#define NB   4
#define CIN  4
#define COUT 4
#define KS   5
#define KK   (KS*KS)
#define HH   128
#define WW   128
#define HW   (HH*WW)

#define TH    2           // output rows per block (1 per warp)
#define SROWS (TH + 4)    // staged lb rows incl. y-halo
#define NIT   (KS * CIN)  // 20 pipelined iterations (ky-major, cin-minor)

__device__ __forceinline__ float ex2_approx(float x) {
    float y;
    asm("ex2.approx.f32 %0, %1;" : "=f"(y) : "f"(x));
    return y;
}
__device__ __forceinline__ float lg2_approx(float x) {
    float y;
    asm("lg2.approx.f32 %0, %1;" : "=f"(y) : "f"(x));
    return y;
}

__global__ __launch_bounds__(64)
void prop_belief_kernel(const float* __restrict__ lb,
                        const float* __restrict__ lk,
                        float* __restrict__ out)
{
    __shared__ __align__(16) float sh[CIN][SROWS][WW];  // lb*log2e, -inf rows for OOB y

    const int lane = threadIdx.x & 31;
    const int wy   = threadIdx.x >> 5;        // 0..1: row within block
    const int y0   = blockIdx.x * TH;
    const int n    = blockIdx.y >> 2;
    const int cout = blockIdx.y & 3;

    const float LOG2E = 1.4426950408889634f;
    const float LN2   = 0.6931471805599453f;

    // ---- stage lb rows [y0-2, y0+TH+1], aligned float4, no x-halo ----
    for (int i = threadIdx.x; i < CIN * SROWS * (WW / 4); i += 64) {
        const int cin = i / (SROWS * (WW / 4));
        const int rem = i - cin * (SROWS * (WW / 4));
        const int r   = rem / (WW / 4);
        const int c4  = rem - r * (WW / 4);
        const int ys  = y0 - 2 + r;
        float4 v = make_float4(-CUDART_INF_F, -CUDART_INF_F,
                               -CUDART_INF_F, -CUDART_INF_F);
        if (ys >= 0 && ys < HH) {
            const float4 t = *(const float4*)&lb[((n * CIN + cin) * HH + ys) * WW + 4 * c4];
            v = make_float4(t.x * LOG2E, t.y * LOG2E, t.z * LOG2E, t.w * LOG2E);
        }
        *(float4*)&sh[cin][r][4 * c4] = v;
    }
    __syncthreads();

    const int yo = y0 + wy;

    // lk layout: [N][CIN][COUT*KK][H][W]; base at (n, cin=0, cout*KK), this lane's 4 cols
    const float* lkbase = lk + ((size_t)(n * CIN) * (COUT * KK)
                                + (size_t)cout * KK) * HW + 4 * lane;

    // Per-kx accumulators over ALIGNED source columns; x-shift applied at the end.
    float A[KS][4];
    #pragma unroll
    for (int kx = 0; kx < KS; kx++)
        A[kx][0] = A[kx][1] = A[kx][2] = A[kx][3] = 0.f;

    // ---- depth-2 software pipeline over 20 (ky,cin) iterations ----
    // Loads for iteration i+1 issue BEFORE the math of iteration i, so each
    // warp keeps ~5-10 LDG.128 (2.5-5 KB) in flight continuously.
    float4 vbuf[2][KS];
    float4 bbuf[2];

    {   // prologue: it=0 (ky=0, cin=0)
        const int ysc = min(max(yo + 2, 0), HH - 1);
        const float* p = lkbase + (size_t)ysc * WW;
        #pragma unroll
        for (int kx = 0; kx < KS; kx++)
            vbuf[0][kx] = __ldg((const float4*)(p + (size_t)kx * HW));
        bbuf[0] = *(const float4*)&sh[0][wy + 4][4 * lane];
    }

    #pragma unroll
    for (int it = 0; it < NIT; it++) {
        const int cur = it & 1;

        if (it + 1 < NIT) {   // prefetch it+1
            const int ky1  = (it + 1) / CIN;
            const int cin1 = (it + 1) % CIN;
            const int ysc  = min(max(yo + 2 - ky1, 0), HH - 1);
            const float* p = lkbase + ((size_t)cin1 * (COUT * KK)
                                       + (size_t)ky1 * KS) * HW
                                    + (size_t)ysc * WW;
            #pragma unroll
            for (int kx = 0; kx < KS; kx++)
                vbuf[cur ^ 1][kx] = __ldg((const float4*)(p + (size_t)kx * HW));
            bbuf[cur ^ 1] = *(const float4*)&sh[cin1][wy + 4 - ky1][4 * lane];
        }

        const float4 b4 = bbuf[cur];
        #pragma unroll
        for (int kx = 0; kx < KS; kx++) {
            A[kx][0] += ex2_approx(fmaf(vbuf[cur][kx].x, LOG2E, b4.x));
            A[kx][1] += ex2_approx(fmaf(vbuf[cur][kx].y, LOG2E, b4.y));
            A[kx][2] += ex2_approx(fmaf(vbuf[cur][kx].z, LOG2E, b4.z));
            A[kx][3] += ex2_approx(fmaf(vbuf[cur][kx].w, LOG2E, b4.w));
        }
    }

    // ---- combine: out[X] = sum_kx A[kx] at source element X + 2 - kx ----
    const unsigned full = 0xFFFFFFFFu;
    float o0 = A[2][0], o1 = A[2][1], o2 = A[2][2], o3 = A[2][3];   // kx=2, shift 0
    {   // kx=1, shift +1
        float n0 = __shfl_down_sync(full, A[1][0], 1);
        if (lane == 31) n0 = 0.f;
        o0 += A[1][1]; o1 += A[1][2]; o2 += A[1][3]; o3 += n0;
    }
    {   // kx=0, shift +2
        float n0 = __shfl_down_sync(full, A[0][0], 1);
        float n1 = __shfl_down_sync(full, A[0][1], 1);
        if (lane == 31) { n0 = 0.f; n1 = 0.f; }
        o0 += A[0][2]; o1 += A[0][3]; o2 += n0; o3 += n1;
    }
    {   // kx=3, shift -1
        float p3 = __shfl_up_sync(full, A[3][3], 1);
        if (lane == 0) p3 = 0.f;
        o0 += p3; o1 += A[3][0]; o2 += A[3][1]; o3 += A[3][2];
    }
    {   // kx=4, shift -2
        float p2 = __shfl_up_sync(full, A[4][2], 1);
        float p3 = __shfl_up_sync(full, A[4][3], 1);
        if (lane == 0) { p2 = 0.f; p3 = 0.f; }
        o0 += p2; o1 += p3; o2 += A[4][0]; o3 += A[4][1];
    }

    float4 res;
    res.x = lg2_approx(o0) * LN2;
    res.y = lg2_approx(o1) * LN2;
    res.z = lg2_approx(o2) * LN2;
    res.w = lg2_approx(o3) * LN2;
    *(float4*)&out[((n * COUT + cout) * HH + yo) * WW + 4 * lane] = res;
}

extern "C" void kernel_launch(void* const* d_in, const int* in_sizes, int n_in,
                              void* d_out, int out_size)
{
    const float* lb = (const float*)d_in[0];   // (4,4,128,128)
    const float* lk = (const float*)d_in[1];   // (4,4,100,128,128)
    float* out = (float*)d_out;                // (4,4,128,128)

    dim3 block(64);                            // 2 warps = 2 output rows
    dim3 grid(HH / TH, NB * COUT);             // (64, 16) = 1024 CTAs
    prop_belief_kernel<<<grid, block>>>(lb, lk, out);
}